// round 17
// baseline (speedup 1.0000x reference)
#include <cuda_runtime.h>
#include <cuda_bf16.h>
#include <math.h>

typedef unsigned long long ull;
typedef unsigned int u32;
typedef unsigned short u16;

#define Mdim 2048
#define Ndim 256
#define Kdim 256
#define ITERS 1000
#define NS_ITERS 8
#define WS   136           // u16 stride per column (>=128 jj; 68 u32 == 4 mod 32 -> conflict-free)
#define LEV  (8 * WS)      // u16 per level
#define BUFU (2 * LEV)     // u16 per buffer (hi+lo)

// ---------------- scratch (allocation-free rule) ----------------
__device__ float g_G[Ndim * Ndim];
__device__ float g_Atb[Ndim * Kdim];
__device__ float g_X0[Ndim * Ndim];
__device__ float g_X1[Ndim * Ndim];
__device__ float g_Y[Ndim * Ndim];
__device__ float g_a[1];

// ---------------- prologue kernels (validated) ----------------
__global__ void atx_kernel(const float* __restrict__ A, const float* __restrict__ X,
                           float* __restrict__ C, const float* __restrict__ rho_p,
                           int addDiag)
{
    __shared__ float As[32][33];
    __shared__ float Xs[32][33];
    const int tx = threadIdx.x, ty = threadIdx.y;
    const int i0 = blockIdx.x * 32, j0 = blockIdx.y * 32;
    const int m0 = blockIdx.z * (Mdim / 4);
    float acc = 0.f;
    for (int mt = m0; mt < m0 + Mdim / 4; mt += 32) {
        As[ty][tx] = A[(mt + ty) * Ndim + i0 + tx];
        Xs[ty][tx] = X[(mt + ty) * Kdim + j0 + tx];
        __syncthreads();
#pragma unroll
        for (int mm = 0; mm < 32; mm++)
            acc = fmaf(As[mm][ty], Xs[mm][tx], acc);
        __syncthreads();
    }
    const int i = i0 + ty, j = j0 + tx;
    if (addDiag && i == j && blockIdx.z == 0) acc += fabsf(rho_p[0]) + 1e-10f;
    atomicAdd(&C[i * Kdim + j], acc);
}

__global__ void norm_kernel(const float* __restrict__ G, float* __restrict__ a_out)
{
    __shared__ float red[256];
    const int t = threadIdx.x;
    float s = 0.f;
    for (int j = 0; j < Ndim; j++) s += fabsf(G[j * Ndim + t]);
    red[t] = s;
    __syncthreads();
    for (int off = 128; off > 0; off >>= 1) {
        if (t < off) red[t] = fmaxf(red[t], red[t + off]);
        __syncthreads();
    }
    if (t == 0) a_out[0] = 1.0f / red[0];
}

__global__ void init_x_kernel(float* __restrict__ X, const float* __restrict__ a_p)
{
    const int idx = blockIdx.x * blockDim.x + threadIdx.x;
    const int i = idx >> 8, j = idx & 255;
    X[idx] = (i == j) ? a_p[0] : 0.f;
}

__global__ void gemm256_kernel(const float* __restrict__ A, const float* __restrict__ B,
                               float* __restrict__ C, int ns_mode)
{
    __shared__ float As[32][33];
    __shared__ float Bs[32][33];
    const int tx = threadIdx.x, ty = threadIdx.y;
    const int i = blockIdx.y * 32 + ty, j = blockIdx.x * 32 + tx;
    float acc = 0.f;
    for (int kt = 0; kt < Ndim; kt += 32) {
        As[ty][tx] = A[i * Ndim + kt + tx];
        Bs[ty][tx] = B[(kt + ty) * Ndim + j];
        __syncthreads();
#pragma unroll
        for (int mm = 0; mm < 32; mm++)
            acc = fmaf(As[ty][mm], Bs[mm][tx], acc);
        __syncthreads();
    }
    C[i * Ndim + j] = ns_mode ? fmaf(2.f, A[i * Ndim + j], -acc) : acc;
}

// ---------------- helpers ----------------
__device__ __forceinline__ u32 smem_u32(const void* p) {
    u32 a; asm("{ .reg .u64 t; cvta.to.shared.u64 t, %1; cvt.u32.u64 %0, t; }"
               : "=r"(a) : "l"(p));
    return a;
}
__device__ __forceinline__ u32 ctarank() {
    u32 r; asm("mov.u32 %0, %%cluster_ctarank;" : "=r"(r)); return r;
}
__device__ __forceinline__ u32 mapa_to(u32 local, u32 rank) {
    u32 r; asm("mapa.shared::cluster.u32 %0, %1, %2;" : "=r"(r) : "r"(local), "r"(rank));
    return r;
}
__device__ __forceinline__ u16 bfb(float v) {
    return __bfloat16_as_ushort(__float2bfloat16(v));
}
__device__ __forceinline__ float bff(u16 b) {
    return __bfloat162float(__ushort_as_bfloat16(b));
}
__device__ __forceinline__ void split2_pack(float va, float vb, u32& ph, u32& pl) {
    const u16 ha = bfb(va), hb = bfb(vb);
    const u16 la = bfb(va - bff(ha)), lb = bfb(vb - bff(hb));
    ph = (u32)ha | ((u32)hb << 16);
    pl = (u32)la | ((u32)lb << 16);
}
__device__ __forceinline__ void mma16816(float* d, const u32* a, u32 b0, u32 b1) {
    asm volatile(
        "mma.sync.aligned.m16n8k16.row.col.f32.bf16.bf16.f32 "
        "{%0,%1,%2,%3}, {%4,%5,%6,%7}, {%8,%9}, {%0,%1,%2,%3};"
        : "+f"(d[0]), "+f"(d[1]), "+f"(d[2]), "+f"(d[3])
        : "r"(a[0]), "r"(a[1]), "r"(a[2]), "r"(a[3]), "r"(b0), "r"(b1));
}
#define ARRIVE_REL_CL(addr) \
    asm volatile("mbarrier.arrive.release.cluster.shared::cluster.b64 _, [%0];" \
                 :: "r"(addr) : "memory")
#define BAR_WAIT_CL(bar, par) do {                                              \
    u32 _d = 0;                                                                 \
    while (!_d) {                                                               \
        asm volatile("{\n\t.reg .pred p;\n\t"                                   \
            "mbarrier.try_wait.parity.acquire.cluster.shared::cta.b64 p, [%1], %2, 0x989680;\n\t" \
            "selp.b32 %0, 1, 0, p;\n\t}"                                        \
            : "=r"(_d) : "r"(bar), "r"(par) : "memory");                        \
    } } while (0)
#define STS_CL_U16(addr, v) \
    asm volatile("st.shared::cluster.u16 [%0], %1;" :: "r"(addr), "h"(v) : "memory")

// ---------------------------------------------------------------------------
// HMMA ADMM v3b: 4-CTA cluster, all 8 MMA columns real. R16's rel_err~1.0
// was a buffer overflow: WS=72 < 128 jj entries per column -> columns
// overlapped. Fix: WS=136 (same conflict-free residue 4 mod 32 in u32).
// Sync lattice (verified to close through the pbar/wbar chains across all
// 4 CTAs): NO __syncthreads in the loop; all arrives release.cluster.
// CTA rank = 2*mh + jh owns quadrant rows [128mh,+128) x k [128jh,+128);
// 32 MMA/warp/iter (floor 1024 cyc).
// ---------------------------------------------------------------------------
__global__ void __launch_bounds__(256, 1) __cluster_dims__(4, 1, 1)
admm_mma_kernel(const float* __restrict__ Minv, const float* __restrict__ Atb,
                const float* __restrict__ rho_p, const float* __restrict__ lam_p,
                float* __restrict__ out)
{
    __shared__ u16    wsm[2 * BUFU];      // [buf][lev][col*WS + jj]
    __shared__ float2 pbuf[2][256];
    __shared__ ull    pbar, wbar;

    const int tid  = threadIdx.x;
    const int warp = tid >> 5;
    const int lane = tid & 31;
    const int rq   = lane >> 2;          // D/A row-sub AND B col (n)
    const int kq   = lane & 3;
    const u32 rank = ctarank();
    const int mh   = (int)(rank >> 1);
    const int jh   = (int)(rank & 1);
    const int c0   = (blockIdx.x >> 2) * 8;

    const float rho = fabsf(rho_p[0]) + 1e-10f;
    const float tau = fabsf(lam_p[0]) / rho;

    if (tid == 0) {
        asm volatile("mbarrier.init.shared.b64 [%0], %1;"
                     :: "r"(smem_u32(&pbar)), "r"(256) : "memory");
        asm volatile("mbarrier.init.shared.b64 [%0], %1;"
                     :: "r"(smem_u32(&wbar)), "r"(512) : "memory");
    }

    // ---- A fragments: my quadrant, 2 levels in regs (64 u32) ----
    u32 ah[8][4], alo[8][4];
    const int m0 = 128 * mh + 16 * warp + rq;
#pragma unroll
    for (int kt = 0; kt < 8; kt++) {
        const int kg = 128 * jh + 16 * kt + 2 * kq;
        split2_pack(__ldg(Minv + m0 * Ndim + kg),
                    __ldg(Minv + m0 * Ndim + kg + 1), ah[kt][0], alo[kt][0]);
        split2_pack(__ldg(Minv + (m0 + 8) * Ndim + kg),
                    __ldg(Minv + (m0 + 8) * Ndim + kg + 1), ah[kt][1], alo[kt][1]);
        split2_pack(__ldg(Minv + m0 * Ndim + kg + 8),
                    __ldg(Minv + m0 * Ndim + kg + 9), ah[kt][2], alo[kt][2]);
        split2_pack(__ldg(Minv + (m0 + 8) * Ndim + kg + 8),
                    __ldg(Minv + (m0 + 8) * Ndim + kg + 9), ah[kt][3], alo[kt][3]);
    }

    // ---- owned element state: row r_own, cols c0+2kq, +1 ----
    const int r_own = m0 + 8 * jh;       // jh=0 owns lower D row, jh=1 upper
    const float atb0 = __ldg(Atb + r_own * Kdim + c0 + 2 * kq);
    const float atb1 = __ldg(Atb + r_own * Kdim + c0 + 2 * kq + 1);
    float u0 = 0.f, u1 = 0.f, tp0 = 0.f, tp1 = 0.f;

    // ---- initial w = Atb into buf 0 (my k-half rows, 8 cols) ----
    for (int idx = tid; idx < 1024; idx += 256) {
        const int col = idx >> 7, jj = idx & 127;
        const float v = __ldg(Atb + (128 * jh + jj) * Kdim + c0 + col);
        const u16 h = bfb(v), l = bfb(v - bff(h));
        wsm[col * WS + jj]       = h;
        wsm[LEV + col * WS + jj] = l;
    }

    // ---- address plumbing ----
    const int jj_own = 16 * warp + rq + 8 * jh;   // r_own within its k-half
    const u32 wbase  = smem_u32(wsm);
    const u32 tA = mapa_to(wbase, (u32)mh);        // target CTA (0, mh)
    const u32 tB = mapa_to(wbase, (u32)(mh + 2));  // target CTA (1, mh)
    const u32 oh0 = 2u * (u32)((2 * kq) * WS + jj_own);
    const u32 oh1 = 2u * (u32)((2 * kq + 1) * WS + jj_own);
    const u32 ol0 = 2u * (u32)LEV + oh0;
    const u32 ol1 = 2u * (u32)LEV + oh1;
    const u32 wxA = mapa_to(smem_u32(&wbar), (u32)mh);
    const u32 wxB = mapa_to(smem_u32(&wbar), (u32)(mh + 2));
    const u32 jpeer = rank ^ 1u;
    const u32 ppx = mapa_to(smem_u32(&pbar), jpeer);
    u32 my_pb[2], peer_pb[2];
#pragma unroll
    for (int p = 0; p < 2; p++) {
        my_pb[p]   = smem_u32(&pbuf[p][tid]);
        peer_pb[p] = mapa_to(my_pb[p], jpeer);
    }
    const int bbase = rq * (WS / 2) + kq;         // u32 index, level 0 (WS/2=68)
    const u32* wsm32 = (const u32*)wsm;

    __syncthreads();
    asm volatile("barrier.cluster.arrive.aligned;" ::: "memory");
    asm volatile("barrier.cluster.wait.aligned;"   ::: "memory");

    // ---------------- main loop (no CTA barriers) ----------------
    for (int it = 0; it < ITERS; ++it) {
        const u32 par = (u32)(it & 1);
        const int rb  = (it & 1) * (BUFU >> 1);   // u32 offset of read buffer

        float accA[4] = {0.f, 0.f, 0.f, 0.f};
        float accB[4] = {0.f, 0.f, 0.f, 0.f};
        const u32* wh = wsm32 + rb + bbase;
        const u32* wl = wh + (LEV >> 1);
#pragma unroll
        for (int kt = 0; kt < 8; kt++) {
            const u32 bh0 = wh[8 * kt], bh1 = wh[8 * kt + 4];
            const u32 bl0 = wl[8 * kt], bl1 = wl[8 * kt + 4];
            mma16816(accA, ah[kt],  bh0, bh1);    // hh
            mma16816(accA, ah[kt],  bl0, bl1);    // hl
            mma16816(accB, alo[kt], bh0, bh1);    // lh
            mma16816(accB, alo[kt], bl0, bl1);    // ll
        }
        const float d0 = accA[0] + accB[0], d1 = accA[1] + accB[1];
        const float d2 = accA[2] + accB[2], d3 = accA[3] + accB[3];

        // Phase 1: send the NON-owned row pair to the j-peer
        const float s0 = jh ? d0 : d2;
        const float s1 = jh ? d1 : d3;
        asm volatile("st.shared::cluster.v2.f32 [%0], {%1,%2};"
                     :: "r"(peer_pb[par]), "f"(s0), "f"(s1) : "memory");
        ARRIVE_REL_CL(ppx);
        BAR_WAIT_CL(smem_u32(&pbar), par);

        float prx, pry;
        asm volatile("ld.shared.v2.f32 {%0,%1}, [%2];"
                     : "=f"(prx), "=f"(pry) : "r"(my_pb[par]));
        tp0 = (jh ? d2 : d0) + prx;
        tp1 = (jh ? d3 : d1) + pry;

        // z/u update for the owned (row, 2 cols)
        float g, zn, w0, w1;
        g = tp0 + u0; zn = fmaxf(g - tau, 0.f) + fminf(g + tau, 0.f);
        zn = fminf(fmaxf(zn, 0.f), 1.f); u0 += tp0 - zn;
        w0 = fmaf(rho, zn - u0, atb0);
        g = tp1 + u1; zn = fmaxf(g - tau, 0.f) + fminf(g + tau, 0.f);
        zn = fminf(fmaxf(zn, 0.f), 1.f); u1 += tp1 - zn;
        w1 = fmaf(rho, zn - u1, atb1);

        // Phase 2: distribute split w to both jh==mh CTAs
        const u16 h0 = bfb(w0), l0 = bfb(w0 - bff(h0));
        const u16 h1 = bfb(w1), l1 = bfb(w1 - bff(h1));
        const u32 bo = (u32)(((it & 1) ^ 1) * (BUFU * 2));   // write-buffer bytes
        STS_CL_U16(tA + bo + oh0, h0);
        STS_CL_U16(tA + bo + oh1, h1);
        STS_CL_U16(tA + bo + ol0, l0);
        STS_CL_U16(tA + bo + ol1, l1);
        STS_CL_U16(tB + bo + oh0, h0);
        STS_CL_U16(tB + bo + oh1, h1);
        STS_CL_U16(tB + bo + ol0, l0);
        STS_CL_U16(tB + bo + ol1, l1);
        ARRIVE_REL_CL(wxA);
        ARRIVE_REL_CL(wxB);
        BAR_WAIT_CL(smem_u32(&wbar), par);
    }

    out[r_own * Kdim + c0 + 2 * kq]     = tp0;
    out[r_own * Kdim + c0 + 2 * kq + 1] = tp1;

    asm volatile("barrier.cluster.arrive.aligned;" ::: "memory");
    asm volatile("barrier.cluster.wait.aligned;"   ::: "memory");
}

// ---------------------------------------------------------------------------
extern "C" void kernel_launch(void* const* d_in, const int* in_sizes, int n_in,
                              void* d_out, int out_size)
{
    // metadata order: T, s_A, s_mic_data, rho_param, lam_param
    const float* s_A   = (const float*)d_in[1];
    const float* s_mic = (const float*)d_in[2];
    const float* rho_p = (const float*)d_in[3];
    const float* lam_p = (const float*)d_in[4];
    float* out = (float*)d_out;

    float *G, *Atb, *X0, *X1, *Y, *ap;
    cudaGetSymbolAddress((void**)&G,   g_G);
    cudaGetSymbolAddress((void**)&Atb, g_Atb);
    cudaGetSymbolAddress((void**)&X0,  g_X0);
    cudaGetSymbolAddress((void**)&X1,  g_X1);
    cudaGetSymbolAddress((void**)&Y,   g_Y);
    cudaGetSymbolAddress((void**)&ap,  g_a);

    cudaMemsetAsync(G,   0, Ndim * Ndim * sizeof(float));
    cudaMemsetAsync(Atb, 0, Ndim * Kdim * sizeof(float));
    dim3 tb(32, 32);
    dim3 gbz(8, 8, 4);
    atx_kernel<<<gbz, tb>>>(s_A, s_A,   G,   rho_p, 1);
    atx_kernel<<<gbz, tb>>>(s_A, s_mic, Atb, rho_p, 0);

    // Newton-Schulz inverse (fp32): X <- 2X - X@(G@X)
    norm_kernel<<<1, 256>>>(G, ap);
    init_x_kernel<<<256, 256>>>(X0, ap);
    dim3 gb(8, 8);
    float* Xc = X0; float* Xn = X1;
    for (int i = 0; i < NS_ITERS; i++) {
        gemm256_kernel<<<gb, tb>>>(G,  Xc, Y,  0);
        gemm256_kernel<<<gb, tb>>>(Xc, Y,  Xn, 1);
        float* t = Xc; Xc = Xn; Xn = t;
    }

    admm_mma_kernel<<<128, 256>>>(Xc, Atb, rho_p, lam_p, out);
}